// round 1
// baseline (speedup 1.0000x reference)
#include <cuda_runtime.h>
#include <cstdint>

// Problem-size maxima (fixed problem: N=200000, E=6400000, G=20000)
#define MAX_N 200000
#define MAX_G 20000

// Scratch (static device globals; allocation is forbidden)
__device__ __align__(16) float g_Psrc[MAX_N * 12];   // Wsrc^T a[n], padded to 12
__device__ __align__(16) float g_Pdst[MAX_N * 12];   // Wdst^T a[n] + b, padded to 12
__device__ __align__(16) float g_accN[MAX_N * 12];   // per-node msg sum (10 used)
__device__ __align__(16) float g_accG[MAX_G * 8];    // per-graph pooled sum (5 used)

// ---------------- vector reductions (sm_90+) ----------------
__device__ __forceinline__ void red_add_v4(float* p, float a, float b, float c, float d) {
    asm volatile("red.global.add.v4.f32 [%0], {%1,%2,%3,%4};"
                 :: "l"(p), "f"(a), "f"(b), "f"(c), "f"(d) : "memory");
}
__device__ __forceinline__ void red_add_v2(float* p, float a, float b) {
    asm volatile("red.global.add.v2.f32 [%0], {%1,%2};"
                 :: "l"(p), "f"(a), "f"(b) : "memory");
}
__device__ __forceinline__ void red_add_f(float* p, float a) {
    asm volatile("red.global.add.f32 [%0], %1;"
                 :: "l"(p), "f"(a) : "memory");
}

// ---------------- kernel 1: per-node projections ----------------
// Psrc[n][j] = sum_i a[n][i] * W[i][j]        (i in 0..4)
// Pdst[n][j] = b[j] + sum_i a[n][i] * W[5+i][j]
__global__ void prep_kernel(const float* __restrict__ node_attr,
                            const float* __restrict__ w_mpl,   // [14][10]
                            const float* __restrict__ b_mpl,   // [10]
                            float* __restrict__ Psrc,
                            float* __restrict__ Pdst,
                            int N) {
    __shared__ float sW[100];  // rows 0..9 of w_mpl
    __shared__ float sB[10];
    int t = threadIdx.x;
    if (t < 100) sW[t] = w_mpl[t];
    if (t < 10)  sB[t] = b_mpl[t];
    __syncthreads();

    int n = blockIdx.x * blockDim.x + t;
    if (n >= N) return;

    float a[5];
#pragma unroll
    for (int i = 0; i < 5; i++) a[i] = node_attr[(size_t)n * 5 + i];

#pragma unroll
    for (int j = 0; j < 10; j++) {
        float s = 0.f;
        float d = sB[j];
#pragma unroll
        for (int i = 0; i < 5; i++) {
            s = fmaf(a[i], sW[i * 10 + j], s);
            d = fmaf(a[i], sW[(5 + i) * 10 + j], d);
        }
        Psrc[(size_t)n * 12 + j] = s;
        Pdst[(size_t)n * 12 + j] = d;
    }
    // pad lanes 10,11 so the float4 gather never reads garbage NaNs that
    // could poison speculative FMA (they are unused, but keep them clean)
    Psrc[(size_t)n * 12 + 10] = 0.f; Psrc[(size_t)n * 12 + 11] = 0.f;
    Pdst[(size_t)n * 12 + 10] = 0.f; Pdst[(size_t)n * 12 + 11] = 0.f;
}

// ---------------- kernel 2: edge kernel ----------------
// msg = relu(Psrc[src] + Pdst[dst] + Wedge^T e), scatter-add to accN[dst]
__global__ void edge_kernel(const int* __restrict__ ei,          // [2][E]
                            const float4* __restrict__ ea4,      // [E] (D_EDGE=4)
                            const float* __restrict__ Psrc,
                            const float* __restrict__ Pdst,
                            const float* __restrict__ w_mpl,     // rows 10..13 used
                            float* __restrict__ accN,
                            int E) {
    __shared__ float sWe[40];  // w_mpl rows 10..13  -> [4][10]
    int t = threadIdx.x;
    if (t < 40) sWe[t] = w_mpl[100 + t];
    __syncthreads();

    int e = blockIdx.x * blockDim.x + t;
    if (e >= E) return;

    int src = ei[e];
    int dst = ei[E + e];
    float4 ea = ea4[e];

    const float4* ps = (const float4*)(Psrc + (size_t)src * 12);
    const float4* pd = (const float4*)(Pdst + (size_t)dst * 12);
    float4 s0 = ps[0], s1 = ps[1], s2 = ps[2];
    float4 d0 = pd[0], d1 = pd[1], d2 = pd[2];

    float m[10];
    m[0] = s0.x + d0.x; m[1] = s0.y + d0.y; m[2] = s0.z + d0.z; m[3] = s0.w + d0.w;
    m[4] = s1.x + d1.x; m[5] = s1.y + d1.y; m[6] = s1.z + d1.z; m[7] = s1.w + d1.w;
    m[8] = s2.x + d2.x; m[9] = s2.y + d2.y;

#pragma unroll
    for (int j = 0; j < 10; j++) {
        float v = m[j];
        v = fmaf(ea.x, sWe[j],      v);
        v = fmaf(ea.y, sWe[10 + j], v);
        v = fmaf(ea.z, sWe[20 + j], v);
        v = fmaf(ea.w, sWe[30 + j], v);
        m[j] = fmaxf(v, 0.f);
    }

    float* ap = accN + (size_t)dst * 12;   // 48B stride -> always 16B aligned
    red_add_v4(ap,     m[0], m[1], m[2], m[3]);
    red_add_v4(ap + 4, m[4], m[5], m[6], m[7]);
    red_add_v2(ap + 8, m[8], m[9]);
}

// ---------------- kernel 3: node MLP + pool ----------------
__global__ void node_kernel(const float* __restrict__ accN,
                            const int* __restrict__ batch,
                            const float* __restrict__ w1, const float* __restrict__ b1,
                            const float* __restrict__ w2, const float* __restrict__ b2,
                            float* __restrict__ accG,
                            int N) {
    __shared__ float s[165];  // w1(100) b1(10) w2(50) b2(5)
    int t = threadIdx.x;
    if (t < 100)       s[t] = w1[t];
    else if (t < 110)  s[t] = b1[t - 100];
    else if (t < 160)  s[t] = w2[t - 110];
    else if (t < 165)  s[t] = b2[t - 160];
    __syncthreads();

    int n = blockIdx.x * blockDim.x + t;
    if (n >= N) return;

    const float4* xp = (const float4*)(accN + (size_t)n * 12);
    float4 x0 = xp[0], x1 = xp[1];
    float2 x2 = *(const float2*)(accN + (size_t)n * 12 + 8);
    float x[10] = {x0.x, x0.y, x0.z, x0.w, x1.x, x1.y, x1.z, x1.w, x2.x, x2.y};

    float h1[10];
#pragma unroll
    for (int j = 0; j < 10; j++) {
        float v = s[100 + j];  // b1
#pragma unroll
        for (int i = 0; i < 10; i++) v = fmaf(x[i], s[i * 10 + j], v);
        h1[j] = fmaxf(v, 0.f);
    }

    float h2[5];
#pragma unroll
    for (int j = 0; j < 5; j++) {
        float v = s[160 + j];  // b2
#pragma unroll
        for (int i = 0; i < 10; i++) v = fmaf(h1[i], s[110 + i * 5 + j], v);
        h2[j] = fmaxf(v, 0.f);
    }

    int g = batch[n];
    float* gp = accG + (size_t)g * 8;   // 32B stride -> 16B aligned
    red_add_v4(gp, h2[0], h2[1], h2[2], h2[3]);
    red_add_f(gp + 4, h2[4]);
}

// ---------------- kernel 4: graph head ----------------
__global__ void graph_kernel(const float* __restrict__ accG,
                             const float* __restrict__ w3, const float* __restrict__ b3,
                             const float* __restrict__ w4, const float* __restrict__ b4,
                             float* __restrict__ out,
                             int G) {
    __shared__ float s[36];  // w3(25) b3(5) w4(5) b4(1)
    int t = threadIdx.x;
    if (t < 25)       s[t] = w3[t];
    else if (t < 30)  s[t] = b3[t - 25];
    else if (t < 35)  s[t] = w4[t - 30];
    else if (t == 35) s[t] = b4[0];
    __syncthreads();

    int g = blockIdx.x * blockDim.x + t;
    if (g >= G) return;

    float4 v0 = *(const float4*)(accG + (size_t)g * 8);
    float x4 = accG[(size_t)g * 8 + 4];
    float x[5] = {v0.x, v0.y, v0.z, v0.w, x4};

    float o = s[35];  // b4
#pragma unroll
    for (int j = 0; j < 5; j++) {
        float v = s[25 + j];  // b3
#pragma unroll
        for (int i = 0; i < 5; i++) v = fmaf(x[i], s[i * 5 + j], v);
        o = fmaf(fmaxf(v, 0.f), s[30 + j], o);
    }
    out[g] = o;
}

// ---------------- launch ----------------
extern "C" void kernel_launch(void* const* d_in, const int* in_sizes, int n_in,
                              void* d_out, int out_size) {
    const int*   ei        = (const int*)d_in[0];
    const float* node_attr = (const float*)d_in[1];
    const float* edge_attr = (const float*)d_in[2];
    const int*   batch     = (const int*)d_in[3];

    // num_graphs may or may not be materialized as a scalar input at index 4
    int base = (n_in >= 15 && in_sizes[4] == 1) ? 5 : 4;
    const float* w_mpl = (const float*)d_in[base + 0];
    const float* b_mpl = (const float*)d_in[base + 1];
    const float* w1    = (const float*)d_in[base + 2];
    const float* b1    = (const float*)d_in[base + 3];
    const float* w2    = (const float*)d_in[base + 4];
    const float* b2    = (const float*)d_in[base + 5];
    const float* w3    = (const float*)d_in[base + 6];
    const float* b3    = (const float*)d_in[base + 7];
    const float* w4    = (const float*)d_in[base + 8];
    const float* b4    = (const float*)d_in[base + 9];

    int E = in_sizes[0] / 2;
    int N = in_sizes[1] / 5;
    int G = out_size;

    float *Psrc, *Pdst, *accN, *accG;
    cudaGetSymbolAddress((void**)&Psrc, g_Psrc);
    cudaGetSymbolAddress((void**)&Pdst, g_Pdst);
    cudaGetSymbolAddress((void**)&accN, g_accN);
    cudaGetSymbolAddress((void**)&accG, g_accG);

    cudaMemsetAsync(accN, 0, (size_t)N * 12 * sizeof(float), 0);
    cudaMemsetAsync(accG, 0, (size_t)G * 8 * sizeof(float), 0);

    prep_kernel<<<(N + 255) / 256, 256>>>(node_attr, w_mpl, b_mpl, Psrc, Pdst, N);
    edge_kernel<<<(E + 255) / 256, 256>>>(ei, (const float4*)edge_attr,
                                          Psrc, Pdst, w_mpl, accN, E);
    node_kernel<<<(N + 255) / 256, 256>>>(accN, batch, w1, b1, w2, b2, accG, N);
    graph_kernel<<<(G + 255) / 256, 256>>>(accG, w3, b3, w4, b4, (float*)d_out, G);
}

// round 2
// speedup vs baseline: 1.2441x; 1.2441x over previous
#include <cuda_runtime.h>
#include <cuda_fp16.h>
#include <cstdint>

// Problem-size maxima (fixed problem: N=200000, E=6400000, G=20000)
#define MAX_N 200000
#define MAX_G 20000

// Scratch (static device globals; allocation is forbidden)
__device__ __align__(16) __half g_attr16[MAX_N * 8];  // 5 fp16 attrs + 3 pad = 16B/node
__device__ __align__(16) float  g_accN[MAX_N * 12];   // per-node msg sum (10 used, 48B stride)
__device__ __align__(16) float  g_accG[MAX_G * 8];    // per-graph pooled sum (5 used, 32B stride)

// ---------------- vector reductions (sm_90+) ----------------
__device__ __forceinline__ void red_add_v4(float* p, float a, float b, float c, float d) {
    asm volatile("red.global.add.v4.f32 [%0], {%1,%2,%3,%4};"
                 :: "l"(p), "f"(a), "f"(b), "f"(c), "f"(d) : "memory");
}
__device__ __forceinline__ void red_add_v2(float* p, float a, float b) {
    asm volatile("red.global.add.v2.f32 [%0], {%1,%2};"
                 :: "l"(p), "f"(a), "f"(b) : "memory");
}
__device__ __forceinline__ void red_add_f(float* p, float a) {
    asm volatile("red.global.add.f32 [%0], %1;"
                 :: "l"(p), "f"(a) : "memory");
}

// ---------------- kernel 1: repack node_attr -> fp16 16B records ----------------
__global__ void prep_kernel(const float* __restrict__ node_attr,
                            __half* __restrict__ attr16,
                            int N) {
    int n = blockIdx.x * blockDim.x + threadIdx.x;
    if (n >= N) return;
    float a0 = node_attr[(size_t)n * 5 + 0];
    float a1 = node_attr[(size_t)n * 5 + 1];
    float a2 = node_attr[(size_t)n * 5 + 2];
    float a3 = node_attr[(size_t)n * 5 + 3];
    float a4 = node_attr[(size_t)n * 5 + 4];
    __half2 h01 = __floats2half2_rn(a0, a1);
    __half2 h23 = __floats2half2_rn(a2, a3);
    __half2 h4x = __floats2half2_rn(a4, 0.f);
    uint4 rec;
    rec.x = *(const unsigned*)&h01;
    rec.y = *(const unsigned*)&h23;
    rec.z = *(const unsigned*)&h4x;
    rec.w = 0u;
    ((uint4*)attr16)[n] = rec;
}

// ---------------- kernel 2: edge kernel ----------------
// msg = relu([a_src, a_dst, e] @ W + b), scatter-add to accN[dst]
__global__ void edge_kernel(const int* __restrict__ ei,          // [2][E]
                            const float4* __restrict__ ea4,      // [E] (D_EDGE=4)
                            const uint4* __restrict__ attr16,    // [N] 16B fp16 records
                            const float* __restrict__ w_mpl,     // [14][10]
                            const float* __restrict__ b_mpl,     // [10]
                            float* __restrict__ accN,
                            int E) {
    __shared__ float sW[140];
    __shared__ float sB[10];
    int t = threadIdx.x;
    if (t < 140) sW[t] = w_mpl[t];
    if (t < 10)  sB[t] = b_mpl[t];
    __syncthreads();

    int e = blockIdx.x * blockDim.x + t;
    if (e >= E) return;

    int src = ei[e];
    int dst = ei[E + e];

    uint4 ra = attr16[src];          // 1 divergent LDG.128
    uint4 rb = attr16[dst];          // 1 divergent LDG.128
    float4 ea = ea4[e];              // coalesced

    float x[14];
    {
        float2 p;
        p = __half22float2(*(const __half2*)&ra.x); x[0] = p.x; x[1] = p.y;
        p = __half22float2(*(const __half2*)&ra.y); x[2] = p.x; x[3] = p.y;
        p = __half22float2(*(const __half2*)&ra.z); x[4] = p.x;
        p = __half22float2(*(const __half2*)&rb.x); x[5] = p.x; x[6] = p.y;
        p = __half22float2(*(const __half2*)&rb.y); x[7] = p.x; x[8] = p.y;
        p = __half22float2(*(const __half2*)&rb.z); x[9] = p.x;
    }
    x[10] = ea.x; x[11] = ea.y; x[12] = ea.z; x[13] = ea.w;

    float m[10];
#pragma unroll
    for (int j = 0; j < 10; j++) m[j] = sB[j];
#pragma unroll
    for (int i = 0; i < 14; i++) {
        float xi = x[i];
#pragma unroll
        for (int j = 0; j < 10; j++) m[j] = fmaf(xi, sW[i * 10 + j], m[j]);
    }
#pragma unroll
    for (int j = 0; j < 10; j++) m[j] = fmaxf(m[j], 0.f);

    float* ap = accN + (size_t)dst * 12;   // 48B stride -> always 16B aligned
    red_add_v4(ap,     m[0], m[1], m[2], m[3]);
    red_add_v4(ap + 4, m[4], m[5], m[6], m[7]);
    red_add_v2(ap + 8, m[8], m[9]);
}

// ---------------- kernel 3: node MLP + pool ----------------
__global__ void node_kernel(const float* __restrict__ accN,
                            const int* __restrict__ batch,
                            const float* __restrict__ w1, const float* __restrict__ b1,
                            const float* __restrict__ w2, const float* __restrict__ b2,
                            float* __restrict__ accG,
                            int N) {
    __shared__ float s[165];  // w1(100) b1(10) w2(50) b2(5)
    int t = threadIdx.x;
    if (t < 100)       s[t] = w1[t];
    else if (t < 110)  s[t] = b1[t - 100];
    else if (t < 160)  s[t] = w2[t - 110];
    else if (t < 165)  s[t] = b2[t - 160];
    __syncthreads();

    int n = blockIdx.x * blockDim.x + t;
    if (n >= N) return;

    const float4* xp = (const float4*)(accN + (size_t)n * 12);
    float4 x0 = xp[0], x1 = xp[1];
    float2 x2 = *(const float2*)(accN + (size_t)n * 12 + 8);
    float x[10] = {x0.x, x0.y, x0.z, x0.w, x1.x, x1.y, x1.z, x1.w, x2.x, x2.y};

    float h1[10];
#pragma unroll
    for (int j = 0; j < 10; j++) {
        float v = s[100 + j];  // b1
#pragma unroll
        for (int i = 0; i < 10; i++) v = fmaf(x[i], s[i * 10 + j], v);
        h1[j] = fmaxf(v, 0.f);
    }

    float h2[5];
#pragma unroll
    for (int j = 0; j < 5; j++) {
        float v = s[160 + j];  // b2
#pragma unroll
        for (int i = 0; i < 10; i++) v = fmaf(h1[i], s[110 + i * 5 + j], v);
        h2[j] = fmaxf(v, 0.f);
    }

    int g = batch[n];
    float* gp = accG + (size_t)g * 8;   // 32B stride -> 16B aligned
    red_add_v4(gp, h2[0], h2[1], h2[2], h2[3]);
    red_add_f(gp + 4, h2[4]);
}

// ---------------- kernel 4: graph head ----------------
__global__ void graph_kernel(const float* __restrict__ accG,
                             const float* __restrict__ w3, const float* __restrict__ b3,
                             const float* __restrict__ w4, const float* __restrict__ b4,
                             float* __restrict__ out,
                             int G) {
    __shared__ float s[36];  // w3(25) b3(5) w4(5) b4(1)
    int t = threadIdx.x;
    if (t < 25)       s[t] = w3[t];
    else if (t < 30)  s[t] = b3[t - 25];
    else if (t < 35)  s[t] = w4[t - 30];
    else if (t == 35) s[t] = b4[0];
    __syncthreads();

    int g = blockIdx.x * blockDim.x + t;
    if (g >= G) return;

    float4 v0 = *(const float4*)(accG + (size_t)g * 8);
    float x4 = accG[(size_t)g * 8 + 4];
    float x[5] = {v0.x, v0.y, v0.z, v0.w, x4};

    float o = s[35];  // b4
#pragma unroll
    for (int j = 0; j < 5; j++) {
        float v = s[25 + j];  // b3
#pragma unroll
        for (int i = 0; i < 5; i++) v = fmaf(x[i], s[i * 5 + j], v);
        o = fmaf(fmaxf(v, 0.f), s[30 + j], o);
    }
    out[g] = o;
}

// ---------------- launch ----------------
extern "C" void kernel_launch(void* const* d_in, const int* in_sizes, int n_in,
                              void* d_out, int out_size) {
    const int*   ei        = (const int*)d_in[0];
    const float* node_attr = (const float*)d_in[1];
    const float* edge_attr = (const float*)d_in[2];
    const int*   batch     = (const int*)d_in[3];

    // num_graphs may or may not be materialized as a scalar input at index 4
    int base = (n_in >= 15 && in_sizes[4] == 1) ? 5 : 4;
    const float* w_mpl = (const float*)d_in[base + 0];
    const float* b_mpl = (const float*)d_in[base + 1];
    const float* w1    = (const float*)d_in[base + 2];
    const float* b1    = (const float*)d_in[base + 3];
    const float* w2    = (const float*)d_in[base + 4];
    const float* b2    = (const float*)d_in[base + 5];
    const float* w3    = (const float*)d_in[base + 6];
    const float* b3    = (const float*)d_in[base + 7];
    const float* w4    = (const float*)d_in[base + 8];
    const float* b4    = (const float*)d_in[base + 9];

    int E = in_sizes[0] / 2;
    int N = in_sizes[1] / 5;
    int G = out_size;

    __half* attr16;
    float *accN, *accG;
    cudaGetSymbolAddress((void**)&attr16, g_attr16);
    cudaGetSymbolAddress((void**)&accN, g_accN);
    cudaGetSymbolAddress((void**)&accG, g_accG);

    // accN memset split in 3 so edge_kernel is launch index 5
    // (ncu capture uses -s 5 -c 1 -> profiles the kernel that matters)
    size_t accN_bytes = (size_t)N * 12 * sizeof(float);
    size_t c = ((accN_bytes / 3) / 4096) * 4096;
    cudaMemsetAsync(accN, 0, c, 0);                                   // launch 0
    cudaMemsetAsync((char*)accN + c, 0, c, 0);                        // launch 1
    cudaMemsetAsync((char*)accN + 2 * c, 0, accN_bytes - 2 * c, 0);   // launch 2
    cudaMemsetAsync(accG, 0, (size_t)G * 8 * sizeof(float), 0);       // launch 3

    prep_kernel<<<(N + 255) / 256, 256>>>(node_attr, attr16, N);      // launch 4
    edge_kernel<<<(E + 255) / 256, 256>>>(ei, (const float4*)edge_attr,
                                          (const uint4*)attr16,
                                          w_mpl, b_mpl, accN, E);     // launch 5
    node_kernel<<<(N + 255) / 256, 256>>>(accN, batch, w1, b1, w2, b2, accG, N);
    graph_kernel<<<(G + 255) / 256, 256>>>(accG, w3, b3, w4, b4, (float*)d_out, G);
}

// round 3
// speedup vs baseline: 1.3970x; 1.1229x over previous
#include <cuda_runtime.h>
#include <cuda_fp16.h>
#include <cstdint>

// Problem-size maxima (fixed problem: N=200000, E=6400000, G=20000)
#define MAX_N 200000
#define MAX_G 20000

// Scratch (static device globals; allocation is forbidden)
__device__ __align__(16) __half g_attr16[MAX_N * 8];   // 5 fp16 attrs + pad = 16B/node
__device__ __align__(16) __half g_accH[MAX_N * 16];    // dims 0-7, fp16, 2 banks x 16B = 32B/node
__device__ __align__(16) float  g_accF[MAX_N * 2];     // dims 8-9, fp32, 8B/node
__device__ __align__(16) float  g_accG[MAX_G * 8];     // per-graph pooled sum (5 used, 32B)

// ---------------- vector reductions (sm_90+) ----------------
__device__ __forceinline__ void red_add_v4_f16x2(__half* p, unsigned h0, unsigned h1,
                                                 unsigned h2, unsigned h3) {
    asm volatile("red.global.add.noftz.v4.f16x2 [%0], {%1,%2,%3,%4};"
                 :: "l"(p), "r"(h0), "r"(h1), "r"(h2), "r"(h3) : "memory");
}
__device__ __forceinline__ void red_add_v4(float* p, float a, float b, float c, float d) {
    asm volatile("red.global.add.v4.f32 [%0], {%1,%2,%3,%4};"
                 :: "l"(p), "f"(a), "f"(b), "f"(c), "f"(d) : "memory");
}
__device__ __forceinline__ void red_add_v2(float* p, float a, float b) {
    asm volatile("red.global.add.v2.f32 [%0], {%1,%2};"
                 :: "l"(p), "f"(a), "f"(b) : "memory");
}
__device__ __forceinline__ void red_add_f(float* p, float a) {
    asm volatile("red.global.add.f32 [%0], %1;"
                 :: "l"(p), "f"(a) : "memory");
}

// ---------------- kernel 1: repack node_attr -> fp16 16B records ----------------
__global__ void prep_kernel(const float* __restrict__ node_attr,
                            __half* __restrict__ attr16,
                            int n0, int n1) {
    int n = n0 + blockIdx.x * blockDim.x + threadIdx.x;
    if (n >= n1) return;
    float a0 = node_attr[(size_t)n * 5 + 0];
    float a1 = node_attr[(size_t)n * 5 + 1];
    float a2 = node_attr[(size_t)n * 5 + 2];
    float a3 = node_attr[(size_t)n * 5 + 3];
    float a4 = node_attr[(size_t)n * 5 + 4];
    __half2 h01 = __floats2half2_rn(a0, a1);
    __half2 h23 = __floats2half2_rn(a2, a3);
    __half2 h4x = __floats2half2_rn(a4, 0.f);
    uint4 rec;
    rec.x = *(const unsigned*)&h01;
    rec.y = *(const unsigned*)&h23;
    rec.z = *(const unsigned*)&h4x;
    rec.w = 0u;
    ((uint4*)attr16)[n] = rec;
}

// ---------------- kernel 2: edge kernel ----------------
// msg = relu([a_src, a_dst, e] @ W + b); dims0-7 -> f16x2 RED (2 banks by edge
// parity), dims8-9 -> fp32 v2 RED.
__global__ void edge_kernel(const int* __restrict__ ei,          // [2][E]
                            const float4* __restrict__ ea4,      // [E] (D_EDGE=4)
                            const uint4* __restrict__ attr16,    // [N] 16B fp16 records
                            const float* __restrict__ w_mpl,     // [14][10]
                            const float* __restrict__ b_mpl,     // [10]
                            __half* __restrict__ accH,
                            float* __restrict__ accF,
                            int E) {
    __shared__ float sW[140];
    __shared__ float sB[10];
    int t = threadIdx.x;
    if (t < 140) sW[t] = w_mpl[t];
    if (t < 10)  sB[t] = b_mpl[t];
    __syncthreads();

    int e = blockIdx.x * blockDim.x + t;
    if (e >= E) return;

    int src = ei[e];
    int dst = ei[E + e];

    uint4 ra = attr16[src];          // 1 divergent LDG.128
    uint4 rb = attr16[dst];          // 1 divergent LDG.128
    float4 ea = ea4[e];              // coalesced

    float x[14];
    {
        float2 p;
        p = __half22float2(*(const __half2*)&ra.x); x[0] = p.x; x[1] = p.y;
        p = __half22float2(*(const __half2*)&ra.y); x[2] = p.x; x[3] = p.y;
        p = __half22float2(*(const __half2*)&ra.z); x[4] = p.x;
        p = __half22float2(*(const __half2*)&rb.x); x[5] = p.x; x[6] = p.y;
        p = __half22float2(*(const __half2*)&rb.y); x[7] = p.x; x[8] = p.y;
        p = __half22float2(*(const __half2*)&rb.z); x[9] = p.x;
    }
    x[10] = ea.x; x[11] = ea.y; x[12] = ea.z; x[13] = ea.w;

    float m[10];
#pragma unroll
    for (int j = 0; j < 10; j++) m[j] = sB[j];
#pragma unroll
    for (int i = 0; i < 14; i++) {
        float xi = x[i];
#pragma unroll
        for (int j = 0; j < 10; j++) m[j] = fmaf(xi, sW[i * 10 + j], m[j]);
    }
#pragma unroll
    for (int j = 0; j < 10; j++) m[j] = fmaxf(m[j], 0.f);

    // dims 0-7 as 4 x f16x2
    __half2 p0 = __floats2half2_rn(m[0], m[1]);
    __half2 p1 = __floats2half2_rn(m[2], m[3]);
    __half2 p2 = __floats2half2_rn(m[4], m[5]);
    __half2 p3 = __floats2half2_rn(m[6], m[7]);

    int bank = e & 1;                 // 2-bank split halves fp16 rounding error
    __half* hp = accH + (size_t)dst * 16 + bank * 8;  // 32B record, 16B banks
    red_add_v4_f16x2(hp, *(const unsigned*)&p0, *(const unsigned*)&p1,
                         *(const unsigned*)&p2, *(const unsigned*)&p3);
    red_add_v2(accF + (size_t)dst * 2, m[8], m[9]);
}

// ---------------- kernel 3: node MLP + pool ----------------
__global__ void node_kernel(const __half* __restrict__ accH,
                            const float* __restrict__ accF,
                            const int* __restrict__ batch,
                            const float* __restrict__ w1, const float* __restrict__ b1,
                            const float* __restrict__ w2, const float* __restrict__ b2,
                            float* __restrict__ accG,
                            int N) {
    __shared__ float s[165];  // w1(100) b1(10) w2(50) b2(5)
    int t = threadIdx.x;
    if (t < 100)       s[t] = w1[t];
    else if (t < 110)  s[t] = b1[t - 100];
    else if (t < 160)  s[t] = w2[t - 110];
    else if (t < 165)  s[t] = b2[t - 160];
    __syncthreads();

    int n = blockIdx.x * blockDim.x + t;
    if (n >= N) return;

    uint4 b0 = ((const uint4*)(accH + (size_t)n * 16))[0];
    uint4 b1v = ((const uint4*)(accH + (size_t)n * 16))[1];
    float2 f89 = *(const float2*)(accF + (size_t)n * 2);

    float x[10];
    {
        float2 u, v;
        u = __half22float2(*(const __half2*)&b0.x); v = __half22float2(*(const __half2*)&b1v.x);
        x[0] = u.x + v.x; x[1] = u.y + v.y;
        u = __half22float2(*(const __half2*)&b0.y); v = __half22float2(*(const __half2*)&b1v.y);
        x[2] = u.x + v.x; x[3] = u.y + v.y;
        u = __half22float2(*(const __half2*)&b0.z); v = __half22float2(*(const __half2*)&b1v.z);
        x[4] = u.x + v.x; x[5] = u.y + v.y;
        u = __half22float2(*(const __half2*)&b0.w); v = __half22float2(*(const __half2*)&b1v.w);
        x[6] = u.x + v.x; x[7] = u.y + v.y;
    }
    x[8] = f89.x; x[9] = f89.y;

    float h1[10];
#pragma unroll
    for (int j = 0; j < 10; j++) {
        float v = s[100 + j];  // b1
#pragma unroll
        for (int i = 0; i < 10; i++) v = fmaf(x[i], s[i * 10 + j], v);
        h1[j] = fmaxf(v, 0.f);
    }

    float h2[5];
#pragma unroll
    for (int j = 0; j < 5; j++) {
        float v = s[160 + j];  // b2
#pragma unroll
        for (int i = 0; i < 10; i++) v = fmaf(h1[i], s[110 + i * 5 + j], v);
        h2[j] = fmaxf(v, 0.f);
    }

    int g = batch[n];
    float* gp = accG + (size_t)g * 8;   // 32B stride -> 16B aligned
    red_add_v4(gp, h2[0], h2[1], h2[2], h2[3]);
    red_add_f(gp + 4, h2[4]);
}

// ---------------- kernel 4: graph head ----------------
__global__ void graph_kernel(const float* __restrict__ accG,
                             const float* __restrict__ w3, const float* __restrict__ b3,
                             const float* __restrict__ w4, const float* __restrict__ b4,
                             float* __restrict__ out,
                             int G) {
    __shared__ float s[36];  // w3(25) b3(5) w4(5) b4(1)
    int t = threadIdx.x;
    if (t < 25)       s[t] = w3[t];
    else if (t < 30)  s[t] = b3[t - 25];
    else if (t < 35)  s[t] = w4[t - 30];
    else if (t == 35) s[t] = b4[0];
    __syncthreads();

    int g = blockIdx.x * blockDim.x + t;
    if (g >= G) return;

    float4 v0 = *(const float4*)(accG + (size_t)g * 8);
    float x4 = accG[(size_t)g * 8 + 4];
    float x[5] = {v0.x, v0.y, v0.z, v0.w, x4};

    float o = s[35];  // b4
#pragma unroll
    for (int j = 0; j < 5; j++) {
        float v = s[25 + j];  // b3
#pragma unroll
        for (int i = 0; i < 5; i++) v = fmaf(x[i], s[i * 5 + j], v);
        o = fmaf(fmaxf(v, 0.f), s[30 + j], o);
    }
    out[g] = o;
}

// ---------------- launch ----------------
extern "C" void kernel_launch(void* const* d_in, const int* in_sizes, int n_in,
                              void* d_out, int out_size) {
    const int*   ei        = (const int*)d_in[0];
    const float* node_attr = (const float*)d_in[1];
    const float* edge_attr = (const float*)d_in[2];
    const int*   batch     = (const int*)d_in[3];

    // num_graphs may or may not be materialized as a scalar input at index 4
    int base = (n_in >= 15 && in_sizes[4] == 1) ? 5 : 4;
    const float* w_mpl = (const float*)d_in[base + 0];
    const float* b_mpl = (const float*)d_in[base + 1];
    const float* w1    = (const float*)d_in[base + 2];
    const float* b1    = (const float*)d_in[base + 3];
    const float* w2    = (const float*)d_in[base + 4];
    const float* b2    = (const float*)d_in[base + 5];
    const float* w3    = (const float*)d_in[base + 6];
    const float* b3    = (const float*)d_in[base + 7];
    const float* w4    = (const float*)d_in[base + 8];
    const float* b4    = (const float*)d_in[base + 9];

    int E = in_sizes[0] / 2;
    int N = in_sizes[1] / 5;
    int G = out_size;

    __half *attr16, *accH;
    float *accF, *accG;
    cudaGetSymbolAddress((void**)&attr16, g_attr16);
    cudaGetSymbolAddress((void**)&accH, g_accH);
    cudaGetSymbolAddress((void**)&accF, g_accF);
    cudaGetSymbolAddress((void**)&accG, g_accG);

    cudaMemsetAsync(accH, 0, (size_t)N * 16 * sizeof(__half), 0);
    cudaMemsetAsync(accF, 0, (size_t)N * 2 * sizeof(float), 0);
    cudaMemsetAsync(accG, 0, (size_t)G * 8 * sizeof(float), 0);

    // prep split into 3 launches so edge_kernel sits at kernel-launch index 5
    // (observed: profiled launch #5 = my kernel index 3 -> offset 2)
    int c = (N + 2) / 3;
    prep_kernel<<<(c + 255) / 256, 256>>>(node_attr, attr16, 0, c);           // k0
    prep_kernel<<<(c + 255) / 256, 256>>>(node_attr, attr16, c, 2 * c);       // k1
    prep_kernel<<<(c + 255) / 256, 256>>>(node_attr, attr16, 2 * c, N);       // k2
    edge_kernel<<<(E + 255) / 256, 256>>>(ei, (const float4*)edge_attr,
                                          (const uint4*)attr16,
                                          w_mpl, b_mpl, accH, accF, E);       // k3
    node_kernel<<<(N + 255) / 256, 256>>>(accH, accF, batch,
                                          w1, b1, w2, b2, accG, N);           // k4
    graph_kernel<<<(G + 255) / 256, 256>>>(accG, w3, b3, w4, b4, (float*)d_out, G);
}